// round 4
// baseline (speedup 1.0000x reference)
#include <cuda_runtime.h>
#include <cuda_bf16.h>
#include <cstdint>

#define N_VOX 200000
#define C_CH  128
#define BM    128
#define NTILE ((N_VOX + BM - 1) / BM)   // 1563
#define EPSV  1e-5f

// ---------------------------------------------------------------------------
// Global scratch (no cudaMalloc allowed)
__device__ __align__(16) __nv_bfloat16 g_xh[(size_t)(N_VOX + 1) * C_CH];
__device__ __align__(16) __nv_bfloat16 g_xl[(size_t)(N_VOX + 1) * C_CH];
// Wt images: [axis][seg][hi/lo][n=128][k=128], row-major n x k (B^T for mma)
__device__ __align__(16) __nv_bfloat16 g_wt[3 * 3 * 2 * C_CH * C_CH];
__device__ float g_out[(size_t)3 * N_VOX * C_CH];
__device__ float g_sum[3 * C_CH];
__device__ float g_sq [3 * C_CH];
__device__ float g_scale[3 * C_CH];
__device__ float g_shift[3 * C_CH];

// ---------------------------------------------------------------------------
__device__ __forceinline__ uint32_t smem_u32(const void* p) {
    uint32_t a;
    asm("{ .reg .u64 t; cvta.to.shared.u64 t, %1; cvt.u32.u64 %0, t; }"
        : "=r"(a) : "l"(p));
    return a;
}
__device__ __forceinline__ void cp16(uint32_t dst, const void* src) {
    asm volatile("cp.async.cg.shared.global [%0], [%1], 16;"
                 :: "r"(dst), "l"(src));
}
#define CP_COMMIT() asm volatile("cp.async.commit_group;" ::: "memory")
#define CP_WAIT1()  asm volatile("cp.async.wait_group 1;" ::: "memory")
#define CP_WAIT0()  asm volatile("cp.async.wait_group 0;" ::: "memory")

#define LDSM4(R, addr) \
    asm volatile("ldmatrix.sync.aligned.m8n8.x4.shared.b16 {%0,%1,%2,%3}, [%4];" \
        : "=r"((R)[0]), "=r"((R)[1]), "=r"((R)[2]), "=r"((R)[3]) : "r"(addr))

#define MMA16816(D, A, B0, B1) \
    asm volatile("mma.sync.aligned.m16n8k16.row.col.f32.bf16.bf16.f32 " \
        "{%0,%1,%2,%3}, {%4,%5,%6,%7}, {%8,%9}, {%0,%1,%2,%3};" \
        : "+f"((D)[0]), "+f"((D)[1]), "+f"((D)[2]), "+f"((D)[3]) \
        : "r"((A)[0]), "r"((A)[1]), "r"((A)[2]), "r"((A)[3]), "r"(B0), "r"(B1))

// ---------------------------------------------------------------------------
// SMEM layout: per buffer {Ah, Al, Wh, Wl}, each 128 rows x 144B (64 bf16 + pad)
#define MATB   18432                 // 128 * 144
#define BUFB   (4 * MATB)            // 73728
#define OFF_AL MATB
#define OFF_WH (2 * MATB)
#define OFF_WL (3 * MATB)
#define SSUM_OFF (2 * BUFB)          // 147456
#define SM_TOTAL (SSUM_OFF + 1024)   // 148480

// ---------------------------------------------------------------------------
__global__ void init_stats_kernel() {
    int t = threadIdx.x;
    if (t < 3 * C_CH) { g_sum[t] = 0.f; g_sq[t] = 0.f; }
}

// fp32 -> bf16 hi/lo split of features (+ zero sentinel row N)
__global__ __launch_bounds__(256) void convert_kernel(const float* __restrict__ x)
{
    int i = blockIdx.x * blockDim.x + threadIdx.x;
    const int TOTP = (N_VOX + 1) * C_CH / 2;
    if (i >= TOTP) return;
    int j = i * 2;
    float2 v = (j < N_VOX * C_CH) ? *reinterpret_cast<const float2*>(x + j)
                                  : make_float2(0.f, 0.f);
    __nv_bfloat16 hx = __float2bfloat16(v.x);
    __nv_bfloat16 hy = __float2bfloat16(v.y);
    __nv_bfloat16 lx = __float2bfloat16(v.x - __bfloat162float(hx));
    __nv_bfloat16 ly = __float2bfloat16(v.y - __bfloat162float(hy));
    __nv_bfloat162 h; h.x = hx; h.y = hy;
    __nv_bfloat162 l; l.x = lx; l.y = ly;
    *reinterpret_cast<__nv_bfloat162*>(g_xh + j) = h;
    *reinterpret_cast<__nv_bfloat162*>(g_xl + j) = l;
}

// W[a][s][k][n] -> Wt[a][s][hl][n][k] bf16 hi/lo  (B^T, k contiguous)
__global__ __launch_bounds__(256) void wprep_kernel(const float* __restrict__ W)
{
    int gid = blockIdx.x * blockDim.x + threadIdx.x;
    if (gid >= 3 * 3 * C_CH * C_CH) return;
    int as = gid >> 14;                 // a*3+s
    int k  = (gid >> 7) & 127;
    int n  = gid & 127;
    float v = W[gid];
    __nv_bfloat16 h = __float2bfloat16(v);
    __nv_bfloat16 l = __float2bfloat16(v - __bfloat162float(h));
    size_t base = (size_t)(as * 2) * C_CH * C_CH;
    g_wt[base + (size_t)n * C_CH + k] = h;
    g_wt[base + C_CH * C_CH + (size_t)n * C_CH + k] = l;
}

// ---------------------------------------------------------------------------
// cp.async one chunk (seg, k-half): A gathered rows + W tile, hi+lo, into buf
__device__ __forceinline__ void load_chunk(
    uint32_t sbase, int buf, int a, int tile0, int chunk,
    const int* __restrict__ nb)
{
    const int t   = threadIdx.x;
    const int seg = chunk >> 1, kh = chunk & 1;
    const int r   = t >> 1, grp = t & 1;

    int row_g = tile0 + r;
    int idx;
    if (row_g >= N_VOX)      idx = N_VOX;
    else if (seg == 1)       idx = row_g;
    else {
        int side = (seg == 2) ? 1 : 0;
        idx = nb[(size_t)(a * 2 + side) * N_VOX + row_g];
    }
    const char* srcAh = (const char*)(g_xh + (size_t)idx * C_CH + kh * 64);
    const char* srcAl = (const char*)(g_xl + (size_t)idx * C_CH + kh * 64);
    const __nv_bfloat16* wb = g_wt + (size_t)((a * 3 + seg) * 2) * C_CH * C_CH;
    const char* srcWh = (const char*)(wb + (size_t)r * C_CH + kh * 64);
    const char* srcWl = (const char*)(wb + C_CH * C_CH + (size_t)r * C_CH + kh * 64);

    uint32_t dstRow = sbase + buf * BUFB + r * 144;
    #pragma unroll
    for (int j = 0; j < 4; ++j) {
        int c16 = (grp * 4 + j) * 16;
        cp16(dstRow + c16,          srcAh + c16);
        cp16(dstRow + OFF_AL + c16, srcAl + c16);
        cp16(dstRow + OFF_WH + c16, srcWh + c16);
        cp16(dstRow + OFF_WL + c16, srcWl + c16);
    }
}

// ---------------------------------------------------------------------------
__global__ __launch_bounds__(256, 1) void gemm_kernel(const int* __restrict__ nb)
{
    extern __shared__ char smem[];
    const uint32_t sbase = smem_u32(smem);
    const int tid  = threadIdx.x;
    const int lane = tid & 31, wid = tid >> 5;
    const int wm   = wid >> 1, wn = wid & 1;      // 4 x 2 warp grid
    const int a     = blockIdx.y;
    const int tile0 = blockIdx.x * BM;

    float* ssum = (float*)(smem + SSUM_OFF);
    float* ssq  = ssum + C_CH;
    if (tid < C_CH) { ssum[tid] = 0.f; ssq[tid] = 0.f; }

    load_chunk(sbase, 0, a, tile0, 0, nb); CP_COMMIT();
    load_chunk(sbase, 1, a, tile0, 1, nb); CP_COMMIT();

    float c[2][8][4];
    #pragma unroll
    for (int i = 0; i < 2; ++i)
        #pragma unroll
        for (int j = 0; j < 8; ++j)
            #pragma unroll
            for (int e = 0; e < 4; ++e) c[i][j][e] = 0.f;

    // ldmatrix per-lane base addresses (A: m16k16 x4; B: two n8 atoms x4)
    const uint32_t aAddr = sbase +
        (uint32_t)(wm * 32 + (lane & 15)) * 144 + (uint32_t)(lane >> 4) * 16;
    const uint32_t bAddr = sbase + OFF_WH +
        (uint32_t)(wn * 64 + ((lane >> 4) * 8) + (lane & 7)) * 144 +
        (uint32_t)((lane >> 3) & 1) * 16;

    #pragma unroll 1
    for (int ch = 0; ch < 6; ++ch) {
        if (ch < 5) CP_WAIT1(); else CP_WAIT0();
        __syncthreads();
        const uint32_t bo = (uint32_t)(ch & 1) * BUFB;

        #pragma unroll
        for (int kk = 0; kk < 4; ++kk) {
            const uint32_t ka = bo + kk * 32;
            uint32_t ah[2][4], al[2][4], bh[4][4], bl[4][4];
            #pragma unroll
            for (int ma = 0; ma < 2; ++ma) {
                LDSM4(ah[ma], aAddr + ka + ma * 2304);
                LDSM4(al[ma], aAddr + ka + ma * 2304 + OFF_AL);
            }
            #pragma unroll
            for (int p = 0; p < 4; ++p) {
                LDSM4(bh[p], bAddr + ka + p * 2304);
                LDSM4(bl[p], bAddr + ka + p * 2304 + MATB);
            }
            #pragma unroll
            for (int ma = 0; ma < 2; ++ma)
                #pragma unroll
                for (int p = 0; p < 4; ++p) {
                    MMA16816(c[ma][2 * p],     ah[ma], bh[p][0], bh[p][1]);
                    MMA16816(c[ma][2 * p + 1], ah[ma], bh[p][2], bh[p][3]);
                    MMA16816(c[ma][2 * p],     al[ma], bh[p][0], bh[p][1]);
                    MMA16816(c[ma][2 * p + 1], al[ma], bh[p][2], bh[p][3]);
                    MMA16816(c[ma][2 * p],     ah[ma], bl[p][0], bl[p][1]);
                    MMA16816(c[ma][2 * p + 1], ah[ma], bl[p][2], bl[p][3]);
                }
        }
        __syncthreads();
        if (ch + 2 < 6) { load_chunk(sbase, ch & 1, a, tile0, ch + 2, nb); CP_COMMIT(); }
    }

    // ---- epilogue: store pre-BN output + per-channel stats
    float scs[16], scq[16];
    #pragma unroll
    for (int i = 0; i < 16; ++i) { scs[i] = 0.f; scq[i] = 0.f; }

    const int rq = lane >> 2, cq2 = (lane & 3) * 2;
    #pragma unroll
    for (int ma = 0; ma < 2; ++ma) {
        #pragma unroll
        for (int na = 0; na < 8; ++na) {
            float* cc = c[ma][na];
            int r0 = tile0 + wm * 32 + ma * 16 + rq;
            int col = wn * 64 + na * 8 + cq2;
            float* dst = g_out + (size_t)a * N_VOX * C_CH + (size_t)r0 * C_CH + col;
            if (r0 < N_VOX)
                *reinterpret_cast<float2*>(dst) = make_float2(cc[0], cc[1]);
            if (r0 + 8 < N_VOX)
                *reinterpret_cast<float2*>(dst + 8 * C_CH) = make_float2(cc[2], cc[3]);
            scs[na * 2]     += cc[0] + cc[2];
            scs[na * 2 + 1] += cc[1] + cc[3];
            scq[na * 2]     += cc[0] * cc[0] + cc[2] * cc[2];
            scq[na * 2 + 1] += cc[1] * cc[1] + cc[3] * cc[3];
        }
    }
    #pragma unroll
    for (int na = 0; na < 8; ++na) {
        int col = wn * 64 + na * 8 + cq2;
        atomicAdd(&ssum[col],     scs[na * 2]);
        atomicAdd(&ssum[col + 1], scs[na * 2 + 1]);
        atomicAdd(&ssq[col],      scq[na * 2]);
        atomicAdd(&ssq[col + 1],  scq[na * 2 + 1]);
    }
    __syncthreads();
    if (tid < C_CH) {
        atomicAdd(&g_sum[a * C_CH + tid], ssum[tid]);
        atomicAdd(&g_sq [a * C_CH + tid], ssq[tid]);
    }
}

// ---------------------------------------------------------------------------
__global__ void finalize_kernel(const float* __restrict__ gamma,
                                const float* __restrict__ beta)
{
    int t = threadIdx.x;
    if (t >= 3 * C_CH) return;
    float invN = 1.0f / (float)N_VOX;
    float mu  = g_sum[t] * invN;
    float var = g_sq[t] * invN - mu * mu;
    float rs  = rsqrtf(var + EPSV);
    float sc  = rs * gamma[t];
    g_scale[t] = sc;
    g_shift[t] = beta[t] - mu * sc;
}

__global__ __launch_bounds__(256) void final_kernel(
    const float* __restrict__ x, float* __restrict__ out)
{
    int i4 = blockIdx.x * blockDim.x + threadIdx.x;
    const int TOT4 = N_VOX * C_CH / 4;
    if (i4 >= TOT4) return;
    int c = (i4 * 4) & (C_CH - 1);

    float4 xv = reinterpret_cast<const float4*>(x)[i4];
    float r0 = 0.f, r1 = 0.f, r2 = 0.f, r3 = 0.f;
    #pragma unroll
    for (int a = 0; a < 3; ++a) {
        float4 o  = reinterpret_cast<const float4*>(g_out + (size_t)a * N_VOX * C_CH)[i4];
        float4 sc = *reinterpret_cast<const float4*>(&g_scale[a * C_CH + c]);
        float4 sh = *reinterpret_cast<const float4*>(&g_shift[a * C_CH + c]);
        float t0 = o.x * sc.x + sh.x;
        float t1 = o.y * sc.y + sh.y;
        float t2 = o.z * sc.z + sh.z;
        float t3 = o.w * sc.w + sh.w;
        r0 += 1.f / (1.f + __expf(-t0));
        r1 += 1.f / (1.f + __expf(-t1));
        r2 += 1.f / (1.f + __expf(-t2));
        r3 += 1.f / (1.f + __expf(-t3));
    }
    reinterpret_cast<float4*>(out)[i4] =
        make_float4(xv.x * r0, xv.y * r1, xv.z * r2, xv.w * r3);
}

// ---------------------------------------------------------------------------
extern "C" void kernel_launch(void* const* d_in, const int* in_sizes, int n_in,
                              void* d_out, int out_size)
{
    const float* x     = (const float*)d_in[0];   // [N, C]
    const int*   nb    = (const int*)  d_in[1];   // [3, 2, N]
    const float* W     = (const float*)d_in[2];   // [3, 3, C, C]
    const float* gamma = (const float*)d_in[3];   // [3, C]
    const float* beta  = (const float*)d_in[4];   // [3, C]
    float*       out   = (float*)d_out;

    cudaFuncSetAttribute(gemm_kernel,
                         cudaFuncAttributeMaxDynamicSharedMemorySize, SM_TOTAL);

    init_stats_kernel<<<1, 3 * C_CH>>>();
    {
        int totp = (N_VOX + 1) * C_CH / 2;
        convert_kernel<<<(totp + 255) / 256, 256>>>(x);
    }
    wprep_kernel<<<(3 * 3 * C_CH * C_CH + 255) / 256, 256>>>(W);
    gemm_kernel<<<dim3(NTILE, 3), 256, SM_TOTAL>>>(nb);
    finalize_kernel<<<1, 3 * C_CH>>>(gamma, beta);
    final_kernel<<<(N_VOX * C_CH / 4 + 255) / 256, 256>>>(x, out);
}

// round 5
// speedup vs baseline: 1.6563x; 1.6563x over previous
#include <cuda_runtime.h>
#include <cuda_bf16.h>
#include <cstdint>

#define N_VOX 200000
#define C_CH  128
#define BM    128
#define NTILE ((N_VOX + BM - 1) / BM)   // 1563
#define EPSV  1e-5f

#define NCHUNK 12          // 384 / 32
#define MATB   8192        // 128 rows * 64 bytes (32 bf16)
#define BUFB   (4 * MATB)  // Ah, Al, Wh, Wl
#define SSUM_OFF (3 * BUFB)             // 98304
#define SM_TOTAL (SSUM_OFF + 1024)      // 99328 -> 2 CTAs/SM

// ---------------------------------------------------------------------------
// Global scratch (no cudaMalloc allowed)
__device__ __align__(16) __nv_bfloat16 g_xh[(size_t)(N_VOX + 1) * C_CH];
__device__ __align__(16) __nv_bfloat16 g_xl[(size_t)(N_VOX + 1) * C_CH];
// Wt images: [axis*3+seg][hi/lo][n=128][k=128] bf16 (B^T, k contiguous)
__device__ __align__(16) __nv_bfloat16 g_wt[3 * 3 * 2 * C_CH * C_CH];
__device__ float g_out[(size_t)3 * N_VOX * C_CH];
__device__ float g_sum[3 * C_CH];
__device__ float g_sq [3 * C_CH];
__device__ float g_scale[3 * C_CH];
__device__ float g_shift[3 * C_CH];

// ---------------------------------------------------------------------------
__device__ __forceinline__ uint32_t smem_u32(const void* p) {
    uint32_t a;
    asm("{ .reg .u64 t; cvta.to.shared.u64 t, %1; cvt.u32.u64 %0, t; }"
        : "=r"(a) : "l"(p));
    return a;
}
__device__ __forceinline__ void cp16(uint32_t dst, const void* src) {
    asm volatile("cp.async.cg.shared.global [%0], [%1], 16;"
                 :: "r"(dst), "l"(src));
}
#define CP_COMMIT() asm volatile("cp.async.commit_group;" ::: "memory")
#define CP_WAIT2()  asm volatile("cp.async.wait_group 2;" ::: "memory")
#define CP_WAIT1()  asm volatile("cp.async.wait_group 1;" ::: "memory")
#define CP_WAIT0()  asm volatile("cp.async.wait_group 0;" ::: "memory")

#define LDSM4(R, addr) \
    asm volatile("ldmatrix.sync.aligned.m8n8.x4.shared.b16 {%0,%1,%2,%3}, [%4];" \
        : "=r"((R)[0]), "=r"((R)[1]), "=r"((R)[2]), "=r"((R)[3]) : "r"(addr))

#define MMA16816(D, A, B0, B1) \
    asm volatile("mma.sync.aligned.m16n8k16.row.col.f32.bf16.bf16.f32 " \
        "{%0,%1,%2,%3}, {%4,%5,%6,%7}, {%8,%9}, {%0,%1,%2,%3};" \
        : "+f"((D)[0]), "+f"((D)[1]), "+f"((D)[2]), "+f"((D)[3]) \
        : "r"((A)[0]), "r"((A)[1]), "r"((A)[2]), "r"((A)[3]), "r"(B0), "r"(B1))

// swizzled byte offset within one 128x64B mat: rows x 4 16B-chunks, XOR spread
__device__ __forceinline__ uint32_t swz(int r, int c) {
    return (uint32_t)(r * 64) + (uint32_t)((c ^ ((r >> 1) & 3)) << 4);
}

// ---------------------------------------------------------------------------
__global__ void init_stats_kernel() {
    int t = threadIdx.x;
    if (t < 3 * C_CH) { g_sum[t] = 0.f; g_sq[t] = 0.f; }
}

// fp32 -> bf16 hi/lo split of features (+ zero sentinel row N)
__global__ __launch_bounds__(256) void convert_kernel(const float* __restrict__ x)
{
    int i = blockIdx.x * blockDim.x + threadIdx.x;
    const int TOTP = (N_VOX + 1) * C_CH / 2;
    if (i >= TOTP) return;
    int j = i * 2;
    float2 v = (j < N_VOX * C_CH) ? *reinterpret_cast<const float2*>(x + j)
                                  : make_float2(0.f, 0.f);
    __nv_bfloat16 hx = __float2bfloat16(v.x);
    __nv_bfloat16 hy = __float2bfloat16(v.y);
    __nv_bfloat16 lx = __float2bfloat16(v.x - __bfloat162float(hx));
    __nv_bfloat16 ly = __float2bfloat16(v.y - __bfloat162float(hy));
    __nv_bfloat162 h; h.x = hx; h.y = hy;
    __nv_bfloat162 l; l.x = lx; l.y = ly;
    *reinterpret_cast<__nv_bfloat162*>(g_xh + j) = h;
    *reinterpret_cast<__nv_bfloat162*>(g_xl + j) = l;
}

// W[a][s][k][n] -> Wt[a*3+s][hl][n][k] bf16 hi/lo
__global__ __launch_bounds__(256) void wprep_kernel(const float* __restrict__ W)
{
    int gid = blockIdx.x * blockDim.x + threadIdx.x;
    if (gid >= 3 * 3 * C_CH * C_CH) return;
    int as = gid >> 14;
    int k  = (gid >> 7) & 127;
    int n  = gid & 127;
    float v = W[gid];
    __nv_bfloat16 h = __float2bfloat16(v);
    __nv_bfloat16 l = __float2bfloat16(v - __bfloat162float(h));
    size_t base = (size_t)(as * 2) * C_CH * C_CH;
    g_wt[base + (size_t)n * C_CH + k] = h;
    g_wt[base + C_CH * C_CH + (size_t)n * C_CH + k] = l;
}

// ---------------------------------------------------------------------------
__global__ __launch_bounds__(256, 2) void gemm_kernel(const int* __restrict__ nb)
{
    extern __shared__ char smem[];
    const uint32_t sbase = smem_u32(smem);
    const int tid  = threadIdx.x;
    const int lane = tid & 31, wid = tid >> 5;
    const int wm   = wid >> 1, wn = wid & 1;      // 4(m) x 2(n) warp grid
    const int a     = blockIdx.y;
    const int tile0 = blockIdx.x * BM;

    float* ssum = (float*)(smem + SSUM_OFF);
    float* ssq  = ssum + C_CH;
    if (tid < C_CH) { ssum[tid] = 0.f; ssq[tid] = 0.f; }

    // per-thread gather indices (row r = tid>>1), loaded once
    const int r_ld  = tid >> 1, half_ld = tid & 1;
    int iSeg[3];
    {
        int row_g = tile0 + r_ld;
        if (row_g >= N_VOX) { iSeg[0] = iSeg[1] = iSeg[2] = N_VOX; }
        else {
            iSeg[0] = nb[(size_t)(a * 2) * N_VOX + row_g];
            iSeg[1] = row_g;
            iSeg[2] = nb[(size_t)(a * 2 + 1) * N_VOX + row_g];
        }
    }
    const char* wbaseA = (const char*)g_wt + (size_t)(a * 3) * 2 * 32768;

    // cp.async one chunk into buffer ch%3
    auto load_chunk = [&](int ch) {
        const int seg = ch >> 2, kq = ch & 3;
        const int idx = iSeg[seg];
        const char* srcA = (const char*)g_xh + (size_t)idx * 256 + kq * 64;
        const char* srcW = wbaseA + (size_t)seg * 2 * 32768 + (size_t)r_ld * 256 + kq * 64;
        const uint32_t bufb = sbase + (uint32_t)(ch % 3) * BUFB;
        #pragma unroll
        for (int j = 0; j < 2; ++j) {
            int c = half_ld * 2 + j;
            uint32_t d = bufb + swz(r_ld, c);
            cp16(d,              srcA + c * 16);
            cp16(d + MATB,       srcA + (size_t)(N_VOX + 1) * 256 * 0 + c * 16 +
                                 ((const char*)g_xl - (const char*)g_xh));
            cp16(d + 2 * MATB,   srcW + c * 16);
            cp16(d + 3 * MATB,   srcW + 32768 + c * 16);
        }
    };

    load_chunk(0); CP_COMMIT();
    load_chunk(1); CP_COMMIT();
    load_chunk(2); CP_COMMIT();

    float c[2][8][4];
    #pragma unroll
    for (int i = 0; i < 2; ++i)
        #pragma unroll
        for (int j = 0; j < 8; ++j)
            #pragma unroll
            for (int e = 0; e < 4; ++e) c[i][j][e] = 0.f;

    // fragment row indices / swizzle phase
    int rA[2], rB[4];
    rA[0] = wm * 32 + (lane & 15); rA[1] = rA[0] + 16;
    #pragma unroll
    for (int p = 0; p < 4; ++p)
        rB[p] = wn * 64 + p * 16 + ((lane >> 4) << 3) + (lane & 7);
    const int cA = lane >> 4;            // 0/1: k16-half chunk
    const int cB = (lane >> 3) & 1;

    #pragma unroll 1
    for (int ch = 0; ch < NCHUNK; ++ch) {
        if (ch < NCHUNK - 2)      CP_WAIT2();
        else if (ch == NCHUNK - 2) CP_WAIT1();
        else                       CP_WAIT0();
        __syncthreads();
        const uint32_t bufb = sbase + (uint32_t)(ch % 3) * BUFB;

        #pragma unroll
        for (int kk = 0; kk < 2; ++kk) {
            uint32_t ah[2][4], al[2][4], bb[4][4];
            #pragma unroll
            for (int ma = 0; ma < 2; ++ma) {
                LDSM4(ah[ma], bufb + swz(rA[ma], kk * 2 + cA));
                LDSM4(al[ma], bufb + MATB + swz(rA[ma], kk * 2 + cA));
            }
            #pragma unroll
            for (int p = 0; p < 4; ++p)
                LDSM4(bb[p], bufb + 2 * MATB + swz(rB[p], kk * 2 + cB));

            // term 0: xh * wh   (16 distinct accumulators back-to-back)
            #pragma unroll
            for (int p = 0; p < 4; ++p)
                #pragma unroll
                for (int ma = 0; ma < 2; ++ma) {
                    MMA16816(c[ma][2 * p],     ah[ma], bb[p][0], bb[p][1]);
                    MMA16816(c[ma][2 * p + 1], ah[ma], bb[p][2], bb[p][3]);
                }
            // term 1: xl * wh
            #pragma unroll
            for (int p = 0; p < 4; ++p)
                #pragma unroll
                for (int ma = 0; ma < 2; ++ma) {
                    MMA16816(c[ma][2 * p],     al[ma], bb[p][0], bb[p][1]);
                    MMA16816(c[ma][2 * p + 1], al[ma], bb[p][2], bb[p][3]);
                }
            // reload B regs with wl, term 2: xh * wl
            #pragma unroll
            for (int p = 0; p < 4; ++p)
                LDSM4(bb[p], bufb + 3 * MATB + swz(rB[p], kk * 2 + cB));
            #pragma unroll
            for (int p = 0; p < 4; ++p)
                #pragma unroll
                for (int ma = 0; ma < 2; ++ma) {
                    MMA16816(c[ma][2 * p],     ah[ma], bb[p][0], bb[p][1]);
                    MMA16816(c[ma][2 * p + 1], ah[ma], bb[p][2], bb[p][3]);
                }
        }
        __syncthreads();
        if (ch + 3 < NCHUNK) { load_chunk(ch + 3); CP_COMMIT(); }
    }

    // ---- epilogue: store pre-BN output + per-channel stats
    float scs[16], scq[16];
    #pragma unroll
    for (int i = 0; i < 16; ++i) { scs[i] = 0.f; scq[i] = 0.f; }

    const int rq = lane >> 2, cq2 = (lane & 3) * 2;
    #pragma unroll
    for (int ma = 0; ma < 2; ++ma) {
        #pragma unroll
        for (int na = 0; na < 8; ++na) {
            float* cc = c[ma][na];
            int r0 = tile0 + wm * 32 + ma * 16 + rq;
            int col = wn * 64 + na * 8 + cq2;
            float* dst = g_out + (size_t)a * N_VOX * C_CH + (size_t)r0 * C_CH + col;
            if (r0 < N_VOX)
                *reinterpret_cast<float2*>(dst) = make_float2(cc[0], cc[1]);
            if (r0 + 8 < N_VOX)
                *reinterpret_cast<float2*>(dst + 8 * C_CH) = make_float2(cc[2], cc[3]);
            scs[na * 2]     += cc[0] + cc[2];
            scs[na * 2 + 1] += cc[1] + cc[3];
            scq[na * 2]     += cc[0] * cc[0] + cc[2] * cc[2];
            scq[na * 2 + 1] += cc[1] * cc[1] + cc[3] * cc[3];
        }
    }
    #pragma unroll
    for (int na = 0; na < 8; ++na) {
        int col = wn * 64 + na * 8 + cq2;
        atomicAdd(&ssum[col],     scs[na * 2]);
        atomicAdd(&ssum[col + 1], scs[na * 2 + 1]);
        atomicAdd(&ssq[col],      scq[na * 2]);
        atomicAdd(&ssq[col + 1],  scq[na * 2 + 1]);
    }
    __syncthreads();
    if (tid < C_CH) {
        atomicAdd(&g_sum[a * C_CH + tid], ssum[tid]);
        atomicAdd(&g_sq [a * C_CH + tid], ssq[tid]);
    }
}

// ---------------------------------------------------------------------------
__global__ void finalize_kernel(const float* __restrict__ gamma,
                                const float* __restrict__ beta)
{
    int t = threadIdx.x;
    if (t >= 3 * C_CH) return;
    float invN = 1.0f / (float)N_VOX;
    float mu  = g_sum[t] * invN;
    float var = g_sq[t] * invN - mu * mu;
    float rs  = rsqrtf(var + EPSV);
    float sc  = rs * gamma[t];
    g_scale[t] = sc;
    g_shift[t] = beta[t] - mu * sc;
}

__global__ __launch_bounds__(256) void final_kernel(
    const float* __restrict__ x, float* __restrict__ out)
{
    int i4 = blockIdx.x * blockDim.x + threadIdx.x;
    const int TOT4 = N_VOX * C_CH / 4;
    if (i4 >= TOT4) return;
    int c = (i4 * 4) & (C_CH - 1);

    float4 xv = reinterpret_cast<const float4*>(x)[i4];
    float r0 = 0.f, r1 = 0.f, r2 = 0.f, r3 = 0.f;
    #pragma unroll
    for (int a = 0; a < 3; ++a) {
        float4 o  = reinterpret_cast<const float4*>(g_out + (size_t)a * N_VOX * C_CH)[i4];
        float4 sc = *reinterpret_cast<const float4*>(&g_scale[a * C_CH + c]);
        float4 sh = *reinterpret_cast<const float4*>(&g_shift[a * C_CH + c]);
        float t0 = o.x * sc.x + sh.x;
        float t1 = o.y * sc.y + sh.y;
        float t2 = o.z * sc.z + sh.z;
        float t3 = o.w * sc.w + sh.w;
        r0 += 1.f / (1.f + __expf(-t0));
        r1 += 1.f / (1.f + __expf(-t1));
        r2 += 1.f / (1.f + __expf(-t2));
        r3 += 1.f / (1.f + __expf(-t3));
    }
    reinterpret_cast<float4*>(out)[i4] =
        make_float4(xv.x * r0, xv.y * r1, xv.z * r2, xv.w * r3);
}

// ---------------------------------------------------------------------------
extern "C" void kernel_launch(void* const* d_in, const int* in_sizes, int n_in,
                              void* d_out, int out_size)
{
    const float* x     = (const float*)d_in[0];   // [N, C]
    const int*   nb    = (const int*)  d_in[1];   // [3, 2, N]
    const float* W     = (const float*)d_in[2];   // [3, 3, C, C]
    const float* gamma = (const float*)d_in[3];   // [3, C]
    const float* beta  = (const float*)d_in[4];   // [3, C]
    float*       out   = (float*)d_out;

    cudaFuncSetAttribute(gemm_kernel,
                         cudaFuncAttributeMaxDynamicSharedMemorySize, SM_TOTAL);

    init_stats_kernel<<<1, 3 * C_CH>>>();
    {
        int totp = (N_VOX + 1) * C_CH / 2;
        convert_kernel<<<(totp + 255) / 256, 256>>>(x);
    }
    wprep_kernel<<<(3 * 3 * C_CH * C_CH + 255) / 256, 256>>>(W);
    gemm_kernel<<<dim3(NTILE, 3), 256, SM_TOTAL>>>(nb);
    finalize_kernel<<<1, 3 * C_CH>>>(gamma, beta);
    final_kernel<<<(N_VOX * C_CH / 4 + 255) / 256, 256>>>(x, out);
}

// round 6
// speedup vs baseline: 3.1660x; 1.9114x over previous
#include <cuda_runtime.h>
#include <cuda_fp16.h>
#include <cstdint>

#define N_VOX 200000
#define C_CH  128
#define BM    128
#define NTILE ((N_VOX + BM - 1) / BM)   // 1563
#define EPSV  1e-5f

#define NCHUNK 12                        // 384 / 32
#define MATB   8192                      // 128 rows * 64 bytes (32 fp16)
#define BUFB   (2 * MATB)                // A + W
#define SSUM_OFF (3 * BUFB)              // 49152
#define SM_TOTAL (SSUM_OFF + 1024)       // 50176 -> 2 CTAs/SM (smem-wise many)

// ---------------------------------------------------------------------------
// Global scratch (no cudaMalloc allowed)
__device__ __align__(16) __half g_xf[(size_t)(N_VOX + 1) * C_CH];
// Wt images: [axis*3+seg][n=128][k=128] fp16 (B^T, k contiguous)
__device__ __align__(16) __half g_wtf[9 * C_CH * C_CH];
__device__ float g_out[(size_t)3 * N_VOX * C_CH];
__device__ float g_sum[3 * C_CH];
__device__ float g_sq [3 * C_CH];
__device__ float g_scale[3 * C_CH];
__device__ float g_shift[3 * C_CH];

// ---------------------------------------------------------------------------
__device__ __forceinline__ uint32_t smem_u32(const void* p) {
    uint32_t a;
    asm("{ .reg .u64 t; cvta.to.shared.u64 t, %1; cvt.u32.u64 %0, t; }"
        : "=r"(a) : "l"(p));
    return a;
}
__device__ __forceinline__ void cp16(uint32_t dst, const void* src) {
    asm volatile("cp.async.cg.shared.global [%0], [%1], 16;"
                 :: "r"(dst), "l"(src));
}
#define CP_COMMIT() asm volatile("cp.async.commit_group;" ::: "memory")
#define CP_WAIT1()  asm volatile("cp.async.wait_group 1;" ::: "memory")
#define CP_WAIT0()  asm volatile("cp.async.wait_group 0;" ::: "memory")

#define LDSM4(R, addr) \
    asm volatile("ldmatrix.sync.aligned.m8n8.x4.shared.b16 {%0,%1,%2,%3}, [%4];" \
        : "=r"((R)[0]), "=r"((R)[1]), "=r"((R)[2]), "=r"((R)[3]) : "r"(addr))

#define MMA16816(D, A, B0, B1) \
    asm volatile("mma.sync.aligned.m16n8k16.row.col.f32.f16.f16.f32 " \
        "{%0,%1,%2,%3}, {%4,%5,%6,%7}, {%8,%9}, {%0,%1,%2,%3};" \
        : "+f"((D)[0]), "+f"((D)[1]), "+f"((D)[2]), "+f"((D)[3]) \
        : "r"((A)[0]), "r"((A)[1]), "r"((A)[2]), "r"((A)[3]), "r"(B0), "r"(B1))

// swizzled byte offset within one 128x64B mat (4 16B chunks per row)
__device__ __forceinline__ uint32_t swz(int r, int c) {
    return (uint32_t)(r * 64) + (uint32_t)((c ^ ((r >> 1) & 3)) << 4);
}

// ---------------------------------------------------------------------------
__global__ void init_stats_kernel() {
    int t = threadIdx.x;
    if (t < 3 * C_CH) { g_sum[t] = 0.f; g_sq[t] = 0.f; }
}

// fp32 -> fp16 features (+ zero sentinel row N)
__global__ __launch_bounds__(256) void convert_kernel(const float* __restrict__ x)
{
    int i = blockIdx.x * blockDim.x + threadIdx.x;
    const int TOTP = (N_VOX + 1) * C_CH / 2;
    if (i >= TOTP) return;
    int j = i * 2;
    float2 v = (j < N_VOX * C_CH) ? *reinterpret_cast<const float2*>(x + j)
                                  : make_float2(0.f, 0.f);
    __half2 h;
    h.x = __float2half_rn(v.x);
    h.y = __float2half_rn(v.y);
    *reinterpret_cast<__half2*>(g_xf + j) = h;
}

// W[a][s][k][n] -> Wt[a*3+s][n][k] fp16
__global__ __launch_bounds__(256) void wprep_kernel(const float* __restrict__ W)
{
    int gid = blockIdx.x * blockDim.x + threadIdx.x;
    if (gid >= 9 * C_CH * C_CH) return;
    int as = gid >> 14;
    int k  = (gid >> 7) & 127;
    int n  = gid & 127;
    g_wtf[(size_t)as * C_CH * C_CH + (size_t)n * C_CH + k] = __float2half_rn(W[gid]);
}

// ---------------------------------------------------------------------------
__global__ __launch_bounds__(512, 2) void gemm_kernel(const int* __restrict__ nb)
{
    extern __shared__ char smem[];
    const uint32_t sbase = smem_u32(smem);
    const int tid  = threadIdx.x;
    const int lane = tid & 31, wid = tid >> 5;
    const int wm   = wid >> 2, wn = wid & 3;      // 4(m) x 4(n) warp grid
    const int a     = blockIdx.y;
    const int tile0 = blockIdx.x * BM;

    float* ssum = (float*)(smem + SSUM_OFF);
    float* ssq  = ssum + C_CH;
    if (tid < C_CH) { ssum[tid] = 0.f; ssq[tid] = 0.f; }

    // per-thread gather indices (row r = tid>>2), loaded once
    const int r_ld = tid >> 2, c_ld = tid & 3;
    int iSeg[3];
    {
        int row_g = tile0 + r_ld;
        if (row_g >= N_VOX) { iSeg[0] = iSeg[1] = iSeg[2] = N_VOX; }
        else {
            iSeg[0] = nb[(size_t)(a * 2) * N_VOX + row_g];
            iSeg[1] = row_g;
            iSeg[2] = nb[(size_t)(a * 2 + 1) * N_VOX + row_g];
        }
    }
    const char* wbaseA = (const char*)g_wtf + (size_t)(a * 3) * 32768;

    // cp.async one chunk (seg = ch>>2, k-quarter = ch&3) into buffer ch%3
    auto load_chunk = [&](int ch) {
        const int seg = ch >> 2, kq = ch & 3;
        const char* srcA = (const char*)g_xf + (size_t)iSeg[seg] * 256 + kq * 64;
        const char* srcW = wbaseA + (size_t)seg * 32768 + (size_t)r_ld * 256 + kq * 64;
        const uint32_t d = sbase + (uint32_t)(ch % 3) * BUFB + swz(r_ld, c_ld);
        cp16(d,        srcA + c_ld * 16);
        cp16(d + MATB, srcW + c_ld * 16);
    };

    load_chunk(0); CP_COMMIT();
    load_chunk(1); CP_COMMIT();

    float c[2][4][4];
    #pragma unroll
    for (int i = 0; i < 2; ++i)
        #pragma unroll
        for (int j = 0; j < 4; ++j)
            #pragma unroll
            for (int e = 0; e < 4; ++e) c[i][j][e] = 0.f;

    // fragment row indices / swizzle column phase
    int rA[2], rB[2];
    rA[0] = wm * 32 + (lane & 15); rA[1] = rA[0] + 16;
    rB[0] = wn * 32 + ((lane >> 4) << 3) + (lane & 7); rB[1] = rB[0] + 16;
    const int cA = lane >> 4;
    const int cB = (lane >> 3) & 1;

    #pragma unroll 1
    for (int ch = 0; ch < NCHUNK; ++ch) {
        if (ch < NCHUNK - 1) CP_WAIT1(); else CP_WAIT0();
        __syncthreads();                               // data ready + prev consume done
        if (ch + 2 < NCHUNK) { load_chunk(ch + 2); CP_COMMIT(); }
        const uint32_t bufb = sbase + (uint32_t)(ch % 3) * BUFB;

        #pragma unroll
        for (int kk = 0; kk < 2; ++kk) {
            uint32_t ah[2][4], bb[2][4];
            #pragma unroll
            for (int ma = 0; ma < 2; ++ma)
                LDSM4(ah[ma], bufb + swz(rA[ma], kk * 2 + cA));
            #pragma unroll
            for (int q = 0; q < 2; ++q)
                LDSM4(bb[q], bufb + MATB + swz(rB[q], kk * 2 + cB));

            #pragma unroll
            for (int q = 0; q < 2; ++q)
                #pragma unroll
                for (int h = 0; h < 2; ++h)
                    #pragma unroll
                    for (int ma = 0; ma < 2; ++ma)
                        MMA16816(c[ma][q * 2 + h], ah[ma],
                                 bb[q][h * 2], bb[q][h * 2 + 1]);
        }
    }

    // ---- epilogue: store pre-BN output + per-channel stats
    float scs[8], scq[8];
    #pragma unroll
    for (int i = 0; i < 8; ++i) { scs[i] = 0.f; scq[i] = 0.f; }

    const int rq = lane >> 2, cq2 = (lane & 3) * 2;
    #pragma unroll
    for (int ma = 0; ma < 2; ++ma) {
        #pragma unroll
        for (int na = 0; na < 4; ++na) {
            float* cc = c[ma][na];
            int r0 = tile0 + wm * 32 + ma * 16 + rq;
            int col = wn * 32 + na * 8 + cq2;
            float* dst = g_out + (size_t)a * N_VOX * C_CH + (size_t)r0 * C_CH + col;
            if (r0 < N_VOX)
                *reinterpret_cast<float2*>(dst) = make_float2(cc[0], cc[1]);
            if (r0 + 8 < N_VOX)
                *reinterpret_cast<float2*>(dst + 8 * C_CH) = make_float2(cc[2], cc[3]);
            scs[na * 2]     += cc[0] + cc[2];
            scs[na * 2 + 1] += cc[1] + cc[3];
            scq[na * 2]     += cc[0] * cc[0] + cc[2] * cc[2];
            scq[na * 2 + 1] += cc[1] * cc[1] + cc[3] * cc[3];
        }
    }
    #pragma unroll
    for (int na = 0; na < 4; ++na) {
        int col = wn * 32 + na * 8 + cq2;
        atomicAdd(&ssum[col],     scs[na * 2]);
        atomicAdd(&ssum[col + 1], scs[na * 2 + 1]);
        atomicAdd(&ssq[col],      scq[na * 2]);
        atomicAdd(&ssq[col + 1],  scq[na * 2 + 1]);
    }
    __syncthreads();
    if (tid < C_CH) {
        atomicAdd(&g_sum[a * C_CH + tid], ssum[tid]);
        atomicAdd(&g_sq [a * C_CH + tid], ssq[tid]);
    }
}

// ---------------------------------------------------------------------------
__global__ void finalize_kernel(const float* __restrict__ gamma,
                                const float* __restrict__ beta)
{
    int t = threadIdx.x;
    if (t >= 3 * C_CH) return;
    float invN = 1.0f / (float)N_VOX;
    float mu  = g_sum[t] * invN;
    float var = g_sq[t] * invN - mu * mu;
    float rs  = rsqrtf(var + EPSV);
    float sc  = rs * gamma[t];
    g_scale[t] = sc;
    g_shift[t] = beta[t] - mu * sc;
}

__global__ __launch_bounds__(256) void final_kernel(
    const float* __restrict__ x, float* __restrict__ out)
{
    int i4 = blockIdx.x * blockDim.x + threadIdx.x;
    const int TOT4 = N_VOX * C_CH / 4;
    if (i4 >= TOT4) return;
    int c = (i4 * 4) & (C_CH - 1);

    float4 xv = reinterpret_cast<const float4*>(x)[i4];
    float r0 = 0.f, r1 = 0.f, r2 = 0.f, r3 = 0.f;
    #pragma unroll
    for (int a = 0; a < 3; ++a) {
        float4 o  = reinterpret_cast<const float4*>(g_out + (size_t)a * N_VOX * C_CH)[i4];
        float4 sc = *reinterpret_cast<const float4*>(&g_scale[a * C_CH + c]);
        float4 sh = *reinterpret_cast<const float4*>(&g_shift[a * C_CH + c]);
        float t0 = o.x * sc.x + sh.x;
        float t1 = o.y * sc.y + sh.y;
        float t2 = o.z * sc.z + sh.z;
        float t3 = o.w * sc.w + sh.w;
        r0 += 1.f / (1.f + __expf(-t0));
        r1 += 1.f / (1.f + __expf(-t1));
        r2 += 1.f / (1.f + __expf(-t2));
        r3 += 1.f / (1.f + __expf(-t3));
    }
    reinterpret_cast<float4*>(out)[i4] =
        make_float4(xv.x * r0, xv.y * r1, xv.z * r2, xv.w * r3);
}

// ---------------------------------------------------------------------------
extern "C" void kernel_launch(void* const* d_in, const int* in_sizes, int n_in,
                              void* d_out, int out_size)
{
    const float* x     = (const float*)d_in[0];   // [N, C]
    const int*   nb    = (const int*)  d_in[1];   // [3, 2, N]
    const float* W     = (const float*)d_in[2];   // [3, 3, C, C]
    const float* gamma = (const float*)d_in[3];   // [3, C]
    const float* beta  = (const float*)d_in[4];   // [3, C]
    float*       out   = (float*)d_out;

    cudaFuncSetAttribute(gemm_kernel,
                         cudaFuncAttributeMaxDynamicSharedMemorySize, SM_TOTAL);

    init_stats_kernel<<<1, 3 * C_CH>>>();
    {
        int totp = (N_VOX + 1) * C_CH / 2;
        convert_kernel<<<(totp + 255) / 256, 256>>>(x);
    }
    wprep_kernel<<<(9 * C_CH * C_CH + 255) / 256, 256>>>(W);
    gemm_kernel<<<dim3(NTILE, 3), 512, SM_TOTAL>>>(nb);
    finalize_kernel<<<1, 3 * C_CH>>>(gamma, beta);
    final_kernel<<<(N_VOX * C_CH / 4 + 255) / 256, 256>>>(x, out);
}